// round 13
// baseline (speedup 1.0000x reference)
#include <cuda_runtime.h>

// pre_spikes [8,1,8192] f32, W [8192,8192] f32, thr [8,1,8192] f32,
// const_inp [8,1,8192] f32 -> out [8,1,8192] f32.
#define BB      8
#define MM      8192
#define NN      8192
#define KSPLIT  64
#define K_TILE  (MM / KSPLIT)     // 128
#define TPB     128
#define VEC     4
#define NCOLS   (TPB * VEC)       // 512 columns per block
#define NTILES  (NN / NCOLS)      // 16
#define HALF    (K_TILE / 2)      // 64 rows per delivery path
#define PREF    8                 // LDG rows per two-phase stage
#define SROWS   8                 // TMA rows per ring slot
#define NSTAGE  3                 // TMA ring slots
#define NSTEPS  (HALF / SROWS)    // 8 mainloop iterations
#define ROW_BYTES   (NCOLS * 4)           // 2048
#define STAGE_BYTES (SROWS * ROW_BYTES)   // 16384
#define RING_BYTES  (NSTAGE * STAGE_BYTES)
#define SPIKE_CAP 0.9f

typedef unsigned long long ull;

// L2-resident accumulator [B][N] = 256 KB (zero invariant across replays).
__device__ float g_accum[(size_t)BB * NN];
// Per-N-tile arrival counters (reset by the finishing block).
__device__ unsigned int g_count[NTILES];

__device__ __forceinline__ void fma2(ull& d, ull a, ull b, ull c) {
    asm("fma.rn.f32x2 %0, %1, %2, %3;" : "=l"(d) : "l"(a), "l"(b), "l"(c));
}
__device__ __forceinline__ void ldcs_v2u64(ull& x, ull& y, const void* p) {
    asm("ld.global.cs.v2.u64 {%0, %1}, [%2];" : "=l"(x), "=l"(y) : "l"(p));
}
__device__ __forceinline__ void redg_v4f32(float* p, ull lo, ull hi) {
    const float2 a = *reinterpret_cast<const float2*>(&lo);
    const float2 b = *reinterpret_cast<const float2*>(&hi);
    asm volatile("red.global.add.v4.f32 [%0], {%1, %2, %3, %4};"
                 :: "l"(p), "f"(a.x), "f"(a.y), "f"(b.x), "f"(b.y)
                 : "memory");
}
__device__ __forceinline__ void bulk_cp(unsigned dst, const void* src,
                                        unsigned bytes, unsigned mbar) {
    asm volatile(
        "cp.async.bulk.shared::cta.global.mbarrier::complete_tx::bytes "
        "[%0], [%1], %2, [%3];"
        :: "r"(dst), "l"(src), "r"(bytes), "r"(mbar) : "memory");
}
__device__ __forceinline__ void mbar_init(unsigned mbar, unsigned count) {
    asm volatile("mbarrier.init.shared.b64 [%0], %1;"
                 :: "r"(mbar), "r"(count) : "memory");
}
__device__ __forceinline__ void mbar_expect_tx(unsigned mbar, unsigned bytes) {
    asm volatile("mbarrier.arrive.expect_tx.shared.b64 _, [%0], %1;"
                 :: "r"(mbar), "r"(bytes) : "memory");
}
__device__ __forceinline__ void mbar_wait(unsigned mbar, unsigned phase) {
    asm volatile(
        "{\n\t"
        ".reg .pred P;\n\t"
        "W%=:\n\t"
        "mbarrier.try_wait.parity.acquire.cta.shared::cta.b64 P, [%0], %1, 0x989680;\n\t"
        "@!P bra W%=;\n\t"
        "}"
        :: "r"(mbar), "r"(phase) : "memory");
}

__global__ __launch_bounds__(TPB)
void snn_fused(const float* __restrict__ pre,
               const float* __restrict__ W,
               const float* __restrict__ thr,
               const float* __restrict__ cinp,
               float* __restrict__ out)
{
    extern __shared__ __align__(128) char ring[];       // 48 KB TMA ring
    __shared__ ull sp2[K_TILE][BB];                      // 8 KB spikes (splat)
    __shared__ __align__(8) ull mbar_s[NSTAGE];
    __shared__ bool s_last;

    const int tid  = threadIdx.x;
    const int ks   = blockIdx.y;
    const int k0   = ks * K_TILE;
    const int tile = blockIdx.x;
    const int nb   = tile * NCOLS;
    const int n0   = nb + tid * VEC;

    const unsigned ring_u32 = (unsigned)__cvta_generic_to_shared(ring);
    const unsigned mbar0    = (unsigned)__cvta_generic_to_shared(&mbar_s[0]);
    // LDG path covers rows [0, HALF); TMA path covers rows [HALF, K_TILE).
    const char*  wldg = reinterpret_cast<const char*>(W + (size_t)k0 * NN + n0);
    const float* wtma = W + (size_t)(k0 + HALF) * NN + nb;

    // ---- TMA: init barriers and launch the first NSTAGE stages now, so the
    // TMA engine streams rows 64.. while warps do everything else. ----
    if (tid == 0) {
        for (int i = 0; i < NSTAGE; i++) mbar_init(mbar0 + 8 * i, 1);
        asm volatile("fence.proxy.async.shared::cta;" ::: "memory");
#pragma unroll
        for (int s = 0; s < NSTAGE; s++) {
            const unsigned mb = mbar0 + 8 * s;
            mbar_expect_tx(mb, STAGE_BYTES);
#pragma unroll
            for (int r = 0; r < SROWS; r++)
                bulk_cp(ring_u32 + s * STAGE_BYTES + r * ROW_BYTES,
                        wtma + (size_t)(s * SROWS + r) * NN, ROW_BYTES, mb);
        }
    }

    for (int i = tid; i < K_TILE * BB; i += TPB) {
        const int b = i >> 7;            // i / K_TILE (K_TILE = 128)
        const int m = i & (K_TILE - 1);
        const float p = pre[(size_t)b * MM + k0 + m];
        ull pk;
        asm("mov.b64 %0, {%1, %1};" : "=l"(pk) : "f"(p));
        sp2[m][b] = pk;
    }
    __syncthreads();   // sp2 ready; mbarrier inits visible to all threads

    ull acc[BB][2];
#pragma unroll
    for (int b = 0; b < BB; b++) { acc[b][0] = 0ULL; acc[b][1] = 0ULL; }

    // FMA block for one row given spikes row m and W (wx, wy).
#define CONSUME_ROW(m, xw, yw)                                                 \
    do {                                                                       \
        const ulonglong2* pv =                                                 \
            reinterpret_cast<const ulonglong2*>(&sp2[(m)][0]);                 \
        const ulonglong2 p01 = pv[0];                                          \
        const ulonglong2 p23 = pv[1];                                          \
        const ulonglong2 p45 = pv[2];                                          \
        const ulonglong2 p67 = pv[3];                                          \
        fma2(acc[0][0], p01.x, (xw), acc[0][0]); fma2(acc[0][1], p01.x, (yw), acc[0][1]); \
        fma2(acc[1][0], p01.y, (xw), acc[1][0]); fma2(acc[1][1], p01.y, (yw), acc[1][1]); \
        fma2(acc[2][0], p23.x, (xw), acc[2][0]); fma2(acc[2][1], p23.x, (yw), acc[2][1]); \
        fma2(acc[3][0], p23.y, (xw), acc[3][0]); fma2(acc[3][1], p23.y, (yw), acc[3][1]); \
        fma2(acc[4][0], p45.x, (xw), acc[4][0]); fma2(acc[4][1], p45.x, (yw), acc[4][1]); \
        fma2(acc[5][0], p45.y, (xw), acc[5][0]); fma2(acc[5][1], p45.y, (yw), acc[5][1]); \
        fma2(acc[6][0], p67.x, (xw), acc[6][0]); fma2(acc[6][1], p67.x, (yw), acc[6][1]); \
        fma2(acc[7][0], p67.y, (xw), acc[7][0]); fma2(acc[7][1], p67.y, (yw), acc[7][1]); \
    } while (0)

    // ---- Mainloop: each iteration moves 8 LDG rows + 8 TMA rows. ----
#pragma unroll 1
    for (int s = 0; s < NSTEPS; s++) {
        // LDG two-phase for rows [s*8, s*8+8) of the LDG half.
        ull wx[PREF], wy[PREF];
#pragma unroll
        for (int j = 0; j < PREF; j++)
            ldcs_v2u64(wx[j], wy[j],
                       wldg + (size_t)(s * PREF + j) * (NN * 4));
#pragma unroll
        for (int j = 0; j < PREF; j++)
            CONSUME_ROW(s * PREF + j, wx[j], wy[j]);

        // TMA slot s: rows [HALF + s*8, HALF + s*8 + 8).
        const int slot = s % NSTAGE;
        const unsigned phase = (unsigned)((s / NSTAGE) & 1);
        mbar_wait(mbar0 + 8 * slot, phase);
        const float* stage =
            reinterpret_cast<const float*>(ring + slot * STAGE_BYTES);
#pragma unroll
        for (int r = 0; r < SROWS; r++) {
            const ulonglong2 w = *reinterpret_cast<const ulonglong2*>(
                stage + r * NCOLS + tid * VEC);
            CONSUME_ROW(HALF + s * SROWS + r, w.x, w.y);
        }

        __syncthreads();   // all warps done reading this slot
        const int si = s + NSTAGE;
        if (si < NSTEPS && tid == 0) {
            asm volatile("fence.proxy.async.shared::cta;" ::: "memory");
            const unsigned mb = mbar0 + 8 * slot;
            mbar_expect_tx(mb, STAGE_BYTES);
#pragma unroll
            for (int r = 0; r < SROWS; r++)
                bulk_cp(ring_u32 + slot * STAGE_BYTES + r * ROW_BYTES,
                        wtma + (size_t)(si * SROWS + r) * NN, ROW_BYTES, mb);
        }
    }
#undef CONSUME_ROW

    // Accumulate partials into the L2-resident accumulator.
#pragma unroll
    for (int b = 0; b < BB; b++) {
        redg_v4f32(&g_accum[(size_t)b * NN + n0], acc[b][0], acc[b][1]);
    }

    // ---- Arrival protocol ----
    __threadfence();
    __syncthreads();
    if (tid == 0) {
        const unsigned int prev = atomicAdd(&g_count[tile], 1u);
        s_last = (prev == KSPLIT - 1);
    }
    __syncthreads();
    if (!s_last) return;

    // ---- Last block of this N-tile: epilogue, 8 batches x 512 columns ----
    __threadfence();

#pragma unroll
    for (int v = 0; v < 8; v++) {
        const int e = (v * TPB + tid) * VEC;           // 0..4095, vec-aligned
        const int b = e >> 9;                          // e / NCOLS
        const int n = nb + (e & (NCOLS - 1));
        const size_t idx = (size_t)b * NN + n;

        float4 s = *reinterpret_cast<const float4*>(&g_accum[idx]);
        const float4 c = *reinterpret_cast<const float4*>(&cinp[idx]);
        const float4 t = *reinterpret_cast<const float4*>(&thr[idx]);
        s.x = fminf(fmaxf(s.x + c.x - t.x, 0.f), SPIKE_CAP);
        s.y = fminf(fmaxf(s.y + c.y - t.y, 0.f), SPIKE_CAP);
        s.z = fminf(fmaxf(s.z + c.z - t.z, 0.f), SPIKE_CAP);
        s.w = fminf(fmaxf(s.w + c.w - t.w, 0.f), SPIKE_CAP);
        *reinterpret_cast<float4*>(&out[idx]) = s;

        *reinterpret_cast<float4*>(&g_accum[idx]) =
            make_float4(0.f, 0.f, 0.f, 0.f);
    }
    if (tid == 0) g_count[tile] = 0u;
}

extern "C" void kernel_launch(void* const* d_in, const int* in_sizes, int n_in,
                              void* d_out, int out_size)
{
    const float* pre  = (const float*)d_in[0];  // pre_spikes [8,1,8192]
    const float* W    = (const float*)d_in[1];  // W [8192,8192]
    const float* thr  = (const float*)d_in[2];  // thr [8,1,8192]
    const float* cinp = (const float*)d_in[3];  // const_inp [8,1,8192]
    float* out = (float*)d_out;

    cudaFuncSetAttribute(snn_fused,
                         cudaFuncAttributeMaxDynamicSharedMemorySize,
                         RING_BYTES);

    dim3 grid(NTILES, KSPLIT);                  // 16 x 64 = 1024 blocks
    snn_fused<<<grid, TPB, RING_BYTES>>>(pre, W, thr, cinp, out);
}

// round 14
// speedup vs baseline: 1.4143x; 1.4143x over previous
#include <cuda_runtime.h>

// pre_spikes [8,1,8192] f32, W [8192,8192] f32, thr [8,1,8192] f32,
// const_inp [8,1,8192] f32 -> out [8,1,8192] f32.
#define BB     8
#define MM     8192
#define NN     8192
#define KSPLIT 64
#define K_TILE (MM / KSPLIT)      // 128
#define TPB    64
#define VEC    8                  // 8 cols/thread -> 32B LDG.256 per row
#define NCOLS  (TPB * VEC)        // 512 columns per block
#define NTILES (NN / NCOLS)       // 16
#define PREF   8                  // W rows prefetched into registers per stage
#define SPIKE_CAP 0.9f

typedef unsigned long long ull;

// L2-resident accumulator [B][N] = 256 KB (zero invariant across replays).
__device__ float g_accum[(size_t)BB * NN];
// Per-N-tile arrival counters (reset by the finishing block).
__device__ unsigned int g_count[NTILES];

// Packed f32x2 FMA (Blackwell): d = a*b + c on both 32-bit halves.
__device__ __forceinline__ void fma2(ull& d, ull a, ull b, ull c) {
    asm("fma.rn.f32x2 %0, %1, %2, %3;" : "=l"(d) : "l"(a), "l"(b), "l"(c));
}

// 32B streaming load (LDG.E.256, Blackwell): 8 floats per instruction.
__device__ __forceinline__ void ldcs_v4u64(ull& x, ull& y, ull& z, ull& w,
                                           const void* p) {
    asm("ld.global.cs.v4.u64 {%0, %1, %2, %3}, [%4];"
        : "=l"(x), "=l"(y), "=l"(z), "=l"(w) : "l"(p));
}

// 16B vector reduction into global (sm_90+): one L2 atomic op per 4 floats.
__device__ __forceinline__ void redg_v4f32(float* p, ull lo, ull hi) {
    const float2 a = *reinterpret_cast<const float2*>(&lo);
    const float2 b = *reinterpret_cast<const float2*>(&hi);
    asm volatile("red.global.add.v4.f32 [%0], {%1, %2, %3, %4};"
                 :: "l"(p), "f"(a.x), "f"(a.y), "f"(b.x), "f"(b.y)
                 : "memory");
}

__global__ __launch_bounds__(TPB)
void snn_fused(const float* __restrict__ pre,
               const float* __restrict__ W,
               const float* __restrict__ thr,
               const float* __restrict__ cinp,
               float* __restrict__ out)
{
    // Pre-spike chunk, each amplitude splatted into both halves of an f32x2.
    __shared__ ull sp2[K_TILE][BB];
    __shared__ bool s_last;

    const int ks = blockIdx.y;
    const int k0 = ks * K_TILE;
    const int tile = blockIdx.x;
    const int n0 = tile * NCOLS + threadIdx.x * VEC;

    for (int i = threadIdx.x; i < K_TILE * BB; i += TPB) {
        const int b = i >> 7;           // i / K_TILE (K_TILE = 128)
        const int m = i & (K_TILE - 1);
        const float p = pre[(size_t)b * MM + k0 + m];
        ull pk;
        asm("mov.b64 %0, {%1, %1};" : "=l"(pk) : "f"(p));
        sp2[m][b] = pk;
    }
    __syncthreads();

    // 8 batches x 8 columns = 32 f32x2 accumulators.
    ull acc[BB][4];
#pragma unroll
    for (int b = 0; b < BB; b++) {
        acc[b][0] = 0ULL; acc[b][1] = 0ULL; acc[b][2] = 0ULL; acc[b][3] = 0ULL;
    }

    const char* wbase = reinterpret_cast<const char*>(W + (size_t)k0 * NN + n0);

    // Two-phase inner loop: front-batch PREF independent LDG.256,
    // then consume with broadcast LDS + FFMA2.
    for (int mb = 0; mb < K_TILE; mb += PREF) {
        ull w0[PREF], w1[PREF], w2[PREF], w3[PREF];
#pragma unroll
        for (int j = 0; j < PREF; j++) {
            ldcs_v4u64(w0[j], w1[j], w2[j], w3[j],
                       wbase + (size_t)(mb + j) * (NN * 4));
        }
#pragma unroll
        for (int j = 0; j < PREF; j++) {
            const ulonglong2* pv =
                reinterpret_cast<const ulonglong2*>(&sp2[mb + j][0]);
            const ulonglong2 p01 = pv[0];             // broadcast LDS.128
            const ulonglong2 p23 = pv[1];
            const ulonglong2 p45 = pv[2];
            const ulonglong2 p67 = pv[3];
            const ull a0 = w0[j], a1 = w1[j], a2 = w2[j], a3 = w3[j];
            fma2(acc[0][0], p01.x, a0, acc[0][0]); fma2(acc[0][1], p01.x, a1, acc[0][1]);
            fma2(acc[0][2], p01.x, a2, acc[0][2]); fma2(acc[0][3], p01.x, a3, acc[0][3]);
            fma2(acc[1][0], p01.y, a0, acc[1][0]); fma2(acc[1][1], p01.y, a1, acc[1][1]);
            fma2(acc[1][2], p01.y, a2, acc[1][2]); fma2(acc[1][3], p01.y, a3, acc[1][3]);
            fma2(acc[2][0], p23.x, a0, acc[2][0]); fma2(acc[2][1], p23.x, a1, acc[2][1]);
            fma2(acc[2][2], p23.x, a2, acc[2][2]); fma2(acc[2][3], p23.x, a3, acc[2][3]);
            fma2(acc[3][0], p23.y, a0, acc[3][0]); fma2(acc[3][1], p23.y, a1, acc[3][1]);
            fma2(acc[3][2], p23.y, a2, acc[3][2]); fma2(acc[3][3], p23.y, a3, acc[3][3]);
            fma2(acc[4][0], p45.x, a0, acc[4][0]); fma2(acc[4][1], p45.x, a1, acc[4][1]);
            fma2(acc[4][2], p45.x, a2, acc[4][2]); fma2(acc[4][3], p45.x, a3, acc[4][3]);
            fma2(acc[5][0], p45.y, a0, acc[5][0]); fma2(acc[5][1], p45.y, a1, acc[5][1]);
            fma2(acc[5][2], p45.y, a2, acc[5][2]); fma2(acc[5][3], p45.y, a3, acc[5][3]);
            fma2(acc[6][0], p67.x, a0, acc[6][0]); fma2(acc[6][1], p67.x, a1, acc[6][1]);
            fma2(acc[6][2], p67.x, a2, acc[6][2]); fma2(acc[6][3], p67.x, a3, acc[6][3]);
            fma2(acc[7][0], p67.y, a0, acc[7][0]); fma2(acc[7][1], p67.y, a1, acc[7][1]);
            fma2(acc[7][2], p67.y, a2, acc[7][2]); fma2(acc[7][3], p67.y, a3, acc[7][3]);
        }
    }

    // Accumulate partials into the L2-resident accumulator.
#pragma unroll
    for (int b = 0; b < BB; b++) {
        redg_v4f32(&g_accum[(size_t)b * NN + n0],     acc[b][0], acc[b][1]);
        redg_v4f32(&g_accum[(size_t)b * NN + n0 + 4], acc[b][2], acc[b][3]);
    }

    // ---- Arrival protocol (threadfence-reduction pattern) ----
    __threadfence();            // make this thread's REDs globally visible
    __syncthreads();            // all threads' REDs+fences precede the bump
    if (threadIdx.x == 0) {
        const unsigned int prev = atomicAdd(&g_count[tile], 1u);
        s_last = (prev == KSPLIT - 1);
    }
    __syncthreads();
    if (!s_last) return;

    // ---- Last block of this N-tile: epilogue, 8 batches x 512 columns ----
    __threadfence();            // acquire: see all other blocks' REDs

    const int nb = tile * NCOLS;
    // 4096 elements = 1024 float4; 16 float4 per thread.
#pragma unroll
    for (int v = 0; v < 16; v++) {
        const int e = (v * TPB + threadIdx.x) * 4;     // 0..4095, vec-aligned
        const int b = e >> 9;                          // e / NCOLS
        const int n = nb + (e & (NCOLS - 1));
        const size_t idx = (size_t)b * NN + n;

        float4 s = *reinterpret_cast<const float4*>(&g_accum[idx]);
        const float4 c = *reinterpret_cast<const float4*>(&cinp[idx]);
        const float4 t = *reinterpret_cast<const float4*>(&thr[idx]);
        s.x = fminf(fmaxf(s.x + c.x - t.x, 0.f), SPIKE_CAP);
        s.y = fminf(fmaxf(s.y + c.y - t.y, 0.f), SPIKE_CAP);
        s.z = fminf(fmaxf(s.z + c.z - t.z, 0.f), SPIKE_CAP);
        s.w = fminf(fmaxf(s.w + c.w - t.w, 0.f), SPIKE_CAP);
        *reinterpret_cast<float4*>(&out[idx]) = s;

        // Restore the zero invariant for the next graph replay.
        *reinterpret_cast<float4*>(&g_accum[idx]) =
            make_float4(0.f, 0.f, 0.f, 0.f);
    }
    if (threadIdx.x == 0) g_count[tile] = 0u;   // reset counter for next call
}

extern "C" void kernel_launch(void* const* d_in, const int* in_sizes, int n_in,
                              void* d_out, int out_size)
{
    const float* pre  = (const float*)d_in[0];  // pre_spikes [8,1,8192]
    const float* W    = (const float*)d_in[1];  // W [8192,8192]
    const float* thr  = (const float*)d_in[2];  // thr [8,1,8192]
    const float* cinp = (const float*)d_in[3];  // const_inp [8,1,8192]
    float* out = (float*)d_out;

    dim3 grid(NTILES, KSPLIT);                  // 16 x 64 = 1024 blocks
    snn_fused<<<grid, TPB>>>(pre, W, thr, cinp, out);
}

// round 15
// speedup vs baseline: 1.6674x; 1.1789x over previous
#include <cuda_runtime.h>

// pre_spikes [8,1,8192] f32, W [8192,8192] f32, thr [8,1,8192] f32,
// const_inp [8,1,8192] f32 -> out [8,1,8192] f32.
#define BB     8
#define MM     8192
#define NN     8192
#define KSPLIT 128
#define K_TILE (MM / KSPLIT)      // 64
#define TPB    64
#define VEC    4
#define NCOLS  (TPB * VEC)        // 256 columns per block
#define NTILES (NN / NCOLS)       // 32
#define PREF   16                 // W rows prefetched into registers per stage
#define SPIKE_CAP 0.9f

typedef unsigned long long ull;

// L2-resident accumulator [B][N] = 256 KB. Zero at load; the finishing block
// of each N-tile re-zeroes its slice every call (graph-replay invariant).
__device__ float g_accum[(size_t)BB * NN];
// Per-N-tile arrival counters (reset by the finishing block).
__device__ unsigned int g_count[NTILES];

// Packed f32x2 FMA (Blackwell): d = a*b + c on both 32-bit halves.
__device__ __forceinline__ void fma2(ull& d, ull a, ull b, ull c) {
    asm("fma.rn.f32x2 %0, %1, %2, %3;" : "=l"(d) : "l"(a), "l"(b), "l"(c));
}

// 16B streaming load (evict-first in L2): W is read exactly once.
__device__ __forceinline__ void ldcs_v2u64(ull& x, ull& y, const void* p) {
    asm("ld.global.cs.v2.u64 {%0, %1}, [%2];" : "=l"(x), "=l"(y) : "l"(p));
}

// 16B vector reduction into global (sm_90+): one L2 atomic op per 4 floats.
__device__ __forceinline__ void redg_v4f32(float* p, ull lo, ull hi) {
    const float2 a = *reinterpret_cast<const float2*>(&lo);
    const float2 b = *reinterpret_cast<const float2*>(&hi);
    asm volatile("red.global.add.v4.f32 [%0], {%1, %2, %3, %4};"
                 :: "l"(p), "f"(a.x), "f"(a.y), "f"(b.x), "f"(b.y)
                 : "memory");
}

__global__ __launch_bounds__(TPB)
void snn_fused(const float* __restrict__ pre,
               const float* __restrict__ W,
               const float* __restrict__ thr,
               const float* __restrict__ cinp,
               float* __restrict__ out)
{
    // Pre-spike chunk, each amplitude splatted into both halves of an f32x2.
    __shared__ ull sp2[K_TILE][BB];
    __shared__ bool s_last;

    const int ks = blockIdx.y;
    const int k0 = ks * K_TILE;
    const int tile = blockIdx.x;
    const int n0 = tile * NCOLS + threadIdx.x * VEC;

    for (int i = threadIdx.x; i < K_TILE * BB; i += TPB) {
        const int b = i >> 6;           // i / K_TILE (K_TILE = 64)
        const int m = i & (K_TILE - 1);
        const float p = pre[(size_t)b * MM + k0 + m];
        ull pk;
        asm("mov.b64 %0, {%1, %1};" : "=l"(pk) : "f"(p));
        sp2[m][b] = pk;
    }
    __syncthreads();

    // 8 batches x 4 columns = 16 f32x2 accumulators.
    ull acc[BB][2];
#pragma unroll
    for (int b = 0; b < BB; b++) { acc[b][0] = 0ULL; acc[b][1] = 0ULL; }

    const char* wbase = reinterpret_cast<const char*>(W + (size_t)k0 * NN + n0);

    // Two-phase inner loop: front-batch PREF independent LDG.128,
    // then consume with broadcast LDS + FFMA2.
    for (int mb = 0; mb < K_TILE; mb += PREF) {
        ull wx[PREF], wy[PREF];
#pragma unroll
        for (int j = 0; j < PREF; j++) {
            ldcs_v2u64(wx[j], wy[j],
                       wbase + (size_t)(mb + j) * (NN * 4));
        }
#pragma unroll
        for (int j = 0; j < PREF; j++) {
            const ulonglong2* pv =
                reinterpret_cast<const ulonglong2*>(&sp2[mb + j][0]);
            const ulonglong2 p01 = pv[0];             // broadcast LDS.128
            const ulonglong2 p23 = pv[1];
            const ulonglong2 p45 = pv[2];
            const ulonglong2 p67 = pv[3];
            const ull xw = wx[j], yw = wy[j];
            fma2(acc[0][0], p01.x, xw, acc[0][0]); fma2(acc[0][1], p01.x, yw, acc[0][1]);
            fma2(acc[1][0], p01.y, xw, acc[1][0]); fma2(acc[1][1], p01.y, yw, acc[1][1]);
            fma2(acc[2][0], p23.x, xw, acc[2][0]); fma2(acc[2][1], p23.x, yw, acc[2][1]);
            fma2(acc[3][0], p23.y, xw, acc[3][0]); fma2(acc[3][1], p23.y, yw, acc[3][1]);
            fma2(acc[4][0], p45.x, xw, acc[4][0]); fma2(acc[4][1], p45.x, yw, acc[4][1]);
            fma2(acc[5][0], p45.y, xw, acc[5][0]); fma2(acc[5][1], p45.y, yw, acc[5][1]);
            fma2(acc[6][0], p67.x, xw, acc[6][0]); fma2(acc[6][1], p67.x, yw, acc[6][1]);
            fma2(acc[7][0], p67.y, xw, acc[7][0]); fma2(acc[7][1], p67.y, yw, acc[7][1]);
        }
    }

    // Accumulate partials into the L2-resident accumulator.
#pragma unroll
    for (int b = 0; b < BB; b++) {
        redg_v4f32(&g_accum[(size_t)b * NN + n0], acc[b][0], acc[b][1]);
    }

    // ---- Arrival protocol (threadfence-reduction pattern) ----
    __threadfence();            // make this thread's REDs globally visible
    __syncthreads();            // all threads' REDs+fences precede the bump
    if (threadIdx.x == 0) {
        const unsigned int prev = atomicAdd(&g_count[tile], 1u);
        s_last = (prev == KSPLIT - 1);
    }
    __syncthreads();
    if (!s_last) return;

    // ---- Last block of this N-tile: epilogue for 8 batches x 256 columns ----
    __threadfence();            // acquire: see all other blocks' REDs

    const int nb = tile * NCOLS;
#pragma unroll
    for (int v = 0; v < 8; v++) {
        const int e = (v * TPB + threadIdx.x) * VEC;   // 0..2047, vec-aligned
        const int b = e >> 8;                          // e / NCOLS
        const int n = nb + (e & (NCOLS - 1));
        const size_t idx = (size_t)b * NN + n;

        float4 s = *reinterpret_cast<const float4*>(&g_accum[idx]);
        const float4 c = *reinterpret_cast<const float4*>(&cinp[idx]);
        const float4 t = *reinterpret_cast<const float4*>(&thr[idx]);
        s.x = fminf(fmaxf(s.x + c.x - t.x, 0.f), SPIKE_CAP);
        s.y = fminf(fmaxf(s.y + c.y - t.y, 0.f), SPIKE_CAP);
        s.z = fminf(fmaxf(s.z + c.z - t.z, 0.f), SPIKE_CAP);
        s.w = fminf(fmaxf(s.w + c.w - t.w, 0.f), SPIKE_CAP);
        *reinterpret_cast<float4*>(&out[idx]) = s;

        // Restore the zero invariant for the next graph replay.
        *reinterpret_cast<float4*>(&g_accum[idx]) =
            make_float4(0.f, 0.f, 0.f, 0.f);
    }
    if (threadIdx.x == 0) g_count[tile] = 0u;   // reset counter for next call
}

extern "C" void kernel_launch(void* const* d_in, const int* in_sizes, int n_in,
                              void* d_out, int out_size)
{
    const float* pre  = (const float*)d_in[0];  // pre_spikes [8,1,8192]
    const float* W    = (const float*)d_in[1];  // W [8192,8192]
    const float* thr  = (const float*)d_in[2];  // thr [8,1,8192]
    const float* cinp = (const float*)d_in[3];  // const_inp [8,1,8192]
    float* out = (float*)d_out;

    dim3 grid(NTILES, KSPLIT);                  // 32 x 128 = 4096 blocks (~2 waves)
    snn_fused<<<grid, TPB>>>(pre, W, thr, cinp, out);
}

// round 16
// speedup vs baseline: 1.7532x; 1.0515x over previous
#include <cuda_runtime.h>

// pre_spikes [8,1,8192] f32, W [8192,8192] f32, thr [8,1,8192] f32,
// const_inp [8,1,8192] f32 -> out [8,1,8192] f32.
#define BB     8
#define MM     8192
#define NN     8192
#define KSPLIT 64
#define K_TILE (MM / KSPLIT)      // 128
#define TPB    64
#define VEC    4
#define NCOLS  (TPB * VEC)        // 256 columns per block
#define NTILES (NN / NCOLS)       // 32
#define PREF   16                 // W rows prefetched into registers per stage
#define SPIKE_CAP 0.9f

typedef unsigned long long ull;

// L2-resident accumulator [B][N] = 256 KB. Zero at load; the finishing block
// of each N-tile re-zeroes its slice every call (graph-replay invariant).
__device__ float g_accum[(size_t)BB * NN];
// Per-N-tile arrival counters (reset by the finishing block).
__device__ unsigned int g_count[NTILES];

// Packed f32x2 FMA (Blackwell): d = a*b + c on both 32-bit halves.
__device__ __forceinline__ void fma2(ull& d, ull a, ull b, ull c) {
    asm("fma.rn.f32x2 %0, %1, %2, %3;" : "=l"(d) : "l"(a), "l"(b), "l"(c));
}

// 16B streaming load (evict-first in L2): W is read exactly once.
__device__ __forceinline__ void ldcs_v2u64(ull& x, ull& y, const void* p) {
    asm("ld.global.cs.v2.u64 {%0, %1}, [%2];" : "=l"(x), "=l"(y) : "l"(p));
}

// 16B vector reduction into global (sm_90+): one L2 atomic op per 4 floats.
__device__ __forceinline__ void redg_v4f32(float* p, ull lo, ull hi) {
    const float2 a = *reinterpret_cast<const float2*>(&lo);
    const float2 b = *reinterpret_cast<const float2*>(&hi);
    asm volatile("red.global.add.v4.f32 [%0], {%1, %2, %3, %4};"
                 :: "l"(p), "f"(a.x), "f"(a.y), "f"(b.x), "f"(b.y)
                 : "memory");
}

__global__ __launch_bounds__(TPB)
void snn_fused(const float* __restrict__ pre,
               const float* __restrict__ W,
               const float* __restrict__ thr,
               const float* __restrict__ cinp,
               float* __restrict__ out)
{
    // Pre-spike chunk, each amplitude splatted into both halves of an f32x2.
    __shared__ ull sp2[K_TILE][BB];
    __shared__ bool s_last;

    const int ks = blockIdx.y;
    const int k0 = ks * K_TILE;
    const int tile = blockIdx.x;
    const int n0 = tile * NCOLS + threadIdx.x * VEC;

    for (int i = threadIdx.x; i < K_TILE * BB; i += TPB) {
        const int b = i >> 7;           // i / K_TILE (K_TILE = 128)
        const int m = i & (K_TILE - 1);
        const float p = pre[(size_t)b * MM + k0 + m];
        ull pk;
        asm("mov.b64 %0, {%1, %1};" : "=l"(pk) : "f"(p));
        sp2[m][b] = pk;
    }
    __syncthreads();

    // 8 batches x 4 columns = 16 f32x2 accumulators.
    ull acc[BB][2];
#pragma unroll
    for (int b = 0; b < BB; b++) { acc[b][0] = 0ULL; acc[b][1] = 0ULL; }

    const char* wbase = reinterpret_cast<const char*>(W + (size_t)k0 * NN + n0);

    // Two-phase inner loop: front-batch PREF independent LDG.128 (MLP=16),
    // then consume with broadcast LDS + FFMA2.
    for (int mb = 0; mb < K_TILE; mb += PREF) {
        ull wx[PREF], wy[PREF];
#pragma unroll
        for (int j = 0; j < PREF; j++) {
            ldcs_v2u64(wx[j], wy[j],
                       wbase + (size_t)(mb + j) * (NN * 4));
        }
#pragma unroll
        for (int j = 0; j < PREF; j++) {
            const ulonglong2* pv =
                reinterpret_cast<const ulonglong2*>(&sp2[mb + j][0]);
            const ulonglong2 p01 = pv[0];
            const ulonglong2 p23 = pv[1];
            const ulonglong2 p45 = pv[2];
            const ulonglong2 p67 = pv[3];
            const ull xw = wx[j], yw = wy[j];
            fma2(acc[0][0], p01.x, xw, acc[0][0]); fma2(acc[0][1], p01.x, yw, acc[0][1]);
            fma2(acc[1][0], p01.y, xw, acc[1][0]); fma2(acc[1][1], p01.y, yw, acc[1][1]);
            fma2(acc[2][0], p23.x, xw, acc[2][0]); fma2(acc[2][1], p23.x, yw, acc[2][1]);
            fma2(acc[3][0], p23.y, xw, acc[3][0]); fma2(acc[3][1], p23.y, yw, acc[3][1]);
            fma2(acc[4][0], p45.x, xw, acc[4][0]); fma2(acc[4][1], p45.x, yw, acc[4][1]);
            fma2(acc[5][0], p45.y, xw, acc[5][0]); fma2(acc[5][1], p45.y, yw, acc[5][1]);
            fma2(acc[6][0], p67.x, xw, acc[6][0]); fma2(acc[6][1], p67.x, yw, acc[6][1]);
            fma2(acc[7][0], p67.y, xw, acc[7][0]); fma2(acc[7][1], p67.y, yw, acc[7][1]);
        }
    }

    // Accumulate partials into the L2-resident accumulator.
#pragma unroll
    for (int b = 0; b < BB; b++) {
        redg_v4f32(&g_accum[(size_t)b * NN + n0], acc[b][0], acc[b][1]);
    }

    // ---- Arrival protocol (threadfence-reduction pattern) ----
    __threadfence();            // make this thread's REDs globally visible
    __syncthreads();            // all threads' REDs+fences precede the bump
    if (threadIdx.x == 0) {
        const unsigned int prev = atomicAdd(&g_count[tile], 1u);
        s_last = (prev == KSPLIT - 1);
    }
    __syncthreads();
    if (!s_last) return;

    // ---- Last block of this N-tile: epilogue for 8 batches x 256 columns ----
    __threadfence();            // acquire: see all other blocks' REDs

    const int nb = tile * NCOLS;
    // 2048 elements = 512 float4; 8 float4 per thread.
#pragma unroll
    for (int v = 0; v < 8; v++) {
        const int e = (v * TPB + threadIdx.x) * VEC;   // 0..2047, vec-aligned
        const int b = e >> 8;                          // e / NCOLS
        const int n = nb + (e & (NCOLS - 1));
        const size_t idx = (size_t)b * NN + n;

        float4 s = *reinterpret_cast<const float4*>(&g_accum[idx]);
        const float4 c = *reinterpret_cast<const float4*>(&cinp[idx]);
        const float4 t = *reinterpret_cast<const float4*>(&thr[idx]);
        s.x = fminf(fmaxf(s.x + c.x - t.x, 0.f), SPIKE_CAP);
        s.y = fminf(fmaxf(s.y + c.y - t.y, 0.f), SPIKE_CAP);
        s.z = fminf(fmaxf(s.z + c.z - t.z, 0.f), SPIKE_CAP);
        s.w = fminf(fmaxf(s.w + c.w - t.w, 0.f), SPIKE_CAP);
        *reinterpret_cast<float4*>(&out[idx]) = s;

        // Restore the zero invariant for the next graph replay.
        *reinterpret_cast<float4*>(&g_accum[idx]) =
            make_float4(0.f, 0.f, 0.f, 0.f);
    }
    if (threadIdx.x == 0) g_count[tile] = 0u;   // reset counter for next call
}

extern "C" void kernel_launch(void* const* d_in, const int* in_sizes, int n_in,
                              void* d_out, int out_size)
{
    const float* pre  = (const float*)d_in[0];  // pre_spikes [8,1,8192]
    const float* W    = (const float*)d_in[1];  // W [8192,8192]
    const float* thr  = (const float*)d_in[2];  // thr [8,1,8192]
    const float* cinp = (const float*)d_in[3];  // const_inp [8,1,8192]
    float* out = (float*)d_out;

    dim3 grid(NTILES, KSPLIT);                  // 32 x 64 = 2048 blocks
    snn_fused<<<grid, TPB>>>(pre, W, thr, cinp, out);
}